// round 2
// baseline (speedup 1.0000x reference)
#include <cuda_runtime.h>

#define N_REL   32
#define N_BASES 30
#define IN_F    64
#define OUT_F   64
#define MAX_NODES 100000
#define MAX_EDGES 1000000
#define TE      128   // edges (rows) per tile

// ---------------- device scratch (static, allocation-free) ----------------
__device__ float g_W[N_REL * IN_F * OUT_F];   // W_r[i][o] = sum_b coeff[r,b]*basis[b,i,o]
__device__ float g_deg[MAX_NODES];
__device__ float g_inv[MAX_NODES];
__device__ int   g_hist[N_REL];
__device__ int   g_off[N_REL + 1];
__device__ int   g_cursor[N_REL];
__device__ int   g_tile_off[N_REL + 1];
__device__ int   g_sorted[MAX_EDGES];

// ---------------- f32x2 / vector-red helpers ----------------
__device__ __forceinline__ unsigned long long f2pack(float lo, float hi) {
    unsigned long long r;
    asm("mov.b64 %0, {%1, %2};" : "=l"(r) : "f"(lo), "f"(hi));
    return r;
}
__device__ __forceinline__ void f2unpack(unsigned long long v, float& lo, float& hi) {
    asm("mov.b64 {%0, %1}, %2;" : "=f"(lo), "=f"(hi) : "l"(v));
}
__device__ __forceinline__ unsigned long long ffma2(unsigned long long a, unsigned long long b,
                                                    unsigned long long c) {
    unsigned long long d;
    asm("fma.rn.f32x2 %0, %1, %2, %3;" : "=l"(d) : "l"(a), "l"(b), "l"(c));
    return d;
}
__device__ __forceinline__ void red4(float* p, float a, float b, float c, float d) {
    asm volatile("red.global.add.v4.f32 [%0], {%1, %2, %3, %4};"
                 :: "l"(p), "f"(a), "f"(b), "f"(c), "f"(d) : "memory");
}

// ---------------- small pipeline kernels ----------------
__global__ void zero_k(int n_nodes) {
    int i = blockIdx.x * blockDim.x + threadIdx.x;
    if (i < n_nodes) g_deg[i] = 0.f;
    if (i < N_REL)   g_hist[i] = 0;
}

__global__ void compute_W_k(const float* __restrict__ basis, const float* __restrict__ coeff) {
    int r = blockIdx.x;
    __shared__ float c[N_BASES];
    if (threadIdx.x < N_BASES) c[threadIdx.x] = coeff[r * N_BASES + threadIdx.x];
    __syncthreads();
    for (int idx = threadIdx.x; idx < IN_F * OUT_F; idx += blockDim.x) {
        float acc = 0.f;
        #pragma unroll
        for (int b = 0; b < N_BASES; b++)
            acc += c[b] * basis[b * IN_F * OUT_F + idx];
        g_W[r * IN_F * OUT_F + idx] = acc;
    }
}

__global__ void hist_deg_k(const int* __restrict__ rel, const int* __restrict__ recv, int E) {
    __shared__ int h[N_REL];
    if (threadIdx.x < N_REL) h[threadIdx.x] = 0;
    __syncthreads();
    for (int e = blockIdx.x * blockDim.x + threadIdx.x; e < E; e += gridDim.x * blockDim.x) {
        atomicAdd(&h[rel[e]], 1);
        atomicAdd(&g_deg[recv[e]], 1.f);
    }
    __syncthreads();
    if (threadIdx.x < N_REL) atomicAdd(&g_hist[threadIdx.x], h[threadIdx.x]);
}

__global__ void prefix_k() {
    int off = 0, toff = 0;
    g_off[0] = 0;
    g_tile_off[0] = 0;
    for (int r = 0; r < N_REL; r++) {
        int c = g_hist[r];
        g_cursor[r] = off;
        off += c;
        g_off[r + 1] = off;
        toff += (c + TE - 1) / TE;
        g_tile_off[r + 1] = toff;
    }
}

__global__ void scatter_k(const int* __restrict__ rel, int E) {
    __shared__ int cnt[N_REL];
    __shared__ int base[N_REL];
    int chunk = (E + gridDim.x - 1) / gridDim.x;
    int s = blockIdx.x * chunk;
    int e_end = min(E, s + chunk);
    if (threadIdx.x < N_REL) cnt[threadIdx.x] = 0;
    __syncthreads();
    for (int i = s + threadIdx.x; i < e_end; i += blockDim.x)
        atomicAdd(&cnt[rel[i]], 1);
    __syncthreads();
    if (threadIdx.x < N_REL)
        base[threadIdx.x] = atomicAdd(&g_cursor[threadIdx.x], cnt[threadIdx.x]);
    __syncthreads();
    if (threadIdx.x < N_REL) cnt[threadIdx.x] = 0;
    __syncthreads();
    for (int i = s + threadIdx.x; i < e_end; i += blockDim.x) {
        int r = rel[i];
        int p = atomicAdd(&cnt[r], 1);
        g_sorted[base[r] + p] = i;
    }
}

__global__ void inv_k(int n) {
    int i = blockIdx.x * blockDim.x + threadIdx.x;
    if (i < n) g_inv[i] = 1.f / fmaxf(g_deg[i], 1.f);
}

// ---------------- shared GEMM micro-kernel ----------------
// 128x64 tile = Xs(128x64) @ Ws(64x64). 256 threads, thread = 4 rows x 8 cols,
// f32x2 packed accumulators. Xs stored with XOR-swizzled float4 chunks so the
// A-operand LDS.128 loads are bank-conflict-free.
__device__ __forceinline__ void gemm_core(const float (&Xs)[TE][IN_F],
                                          const float (&Ws)[IN_F][OUT_F],
                                          int row0, int col0, int sw_x,
                                          unsigned long long (&acc)[4][4]) {
    #pragma unroll
    for (int i = 0; i < 4; i++)
        #pragma unroll
        for (int j = 0; j < 4; j++) acc[i][j] = 0ull;

    for (int k = 0; k < IN_F; k += 4) {
        float4 a[4];
        #pragma unroll
        for (int r4 = 0; r4 < 4; r4++)
            a[r4] = ((const float4*)Xs[row0 + r4])[(k >> 2) ^ sw_x];
        #pragma unroll
        for (int u = 0; u < 4; u++) {
            float4 b0 = *(const float4*)&Ws[k + u][col0];
            float4 b1 = *(const float4*)&Ws[k + u][col0 + 4];
            unsigned long long bp0 = f2pack(b0.x, b0.y);
            unsigned long long bp1 = f2pack(b0.z, b0.w);
            unsigned long long bp2 = f2pack(b1.x, b1.y);
            unsigned long long bp3 = f2pack(b1.z, b1.w);
            #pragma unroll
            for (int r4 = 0; r4 < 4; r4++) {
                float av = (u == 0) ? a[r4].x : (u == 1) ? a[r4].y : (u == 2) ? a[r4].z : a[r4].w;
                unsigned long long ap = f2pack(av, av);
                acc[r4][0] = ffma2(ap, bp0, acc[r4][0]);
                acc[r4][1] = ffma2(ap, bp1, acc[r4][1]);
                acc[r4][2] = ffma2(ap, bp2, acc[r4][2]);
                acc[r4][3] = ffma2(ap, bp3, acc[r4][3]);
            }
        }
    }
}

// ---------------- self term: out = X @ self_weight + bias ----------------
__global__ void __launch_bounds__(256) self_gemm_k(const float* __restrict__ nf,
                                                   const float* __restrict__ sw,
                                                   const float* __restrict__ bias,
                                                   float* __restrict__ out, int N) {
    __shared__ float Xs[TE][IN_F];
    __shared__ float Ws[IN_F][OUT_F];
    int tid = threadIdx.x;
    int base = blockIdx.x * TE;
    int nR = min(TE, N - base);

    {
        const float4* s4 = (const float4*)sw;
        float4* d4 = (float4*)&Ws[0][0];
        for (int i = tid; i < IN_F * OUT_F / 4; i += blockDim.x) d4[i] = s4[i];
    }
    {
        int row = tid & (TE - 1);
        int half = tid >> 7;  // 0 or 1
        if (row < nR) {
            const float4* src = (const float4*)nf + (long long)(base + row) * (IN_F / 4) + half * 8;
            float4* dst = (float4*)Xs[row];
            int swz = (row >> 2) & 3;
            #pragma unroll
            for (int c = 0; c < 8; c++) dst[(half * 8 + c) ^ swz] = src[c];
        }
    }
    __syncthreads();

    int tx = tid & 7, ty = tid >> 3;
    int row0 = ty * 4, col0 = tx * 8;
    unsigned long long acc[4][4];
    gemm_core(Xs, Ws, row0, col0, ty & 3, acc);

    float4 bias0 = *(const float4*)&bias[col0];
    float4 bias1 = *(const float4*)&bias[col0 + 4];
    #pragma unroll
    for (int r4 = 0; r4 < 4; r4++) {
        int row = row0 + r4;
        if (row < nR) {
            float v[8];
            f2unpack(acc[r4][0], v[0], v[1]);
            f2unpack(acc[r4][1], v[2], v[3]);
            f2unpack(acc[r4][2], v[4], v[5]);
            f2unpack(acc[r4][3], v[6], v[7]);
            float4 o0 = make_float4(v[0] + bias0.x, v[1] + bias0.y, v[2] + bias0.z, v[3] + bias0.w);
            float4 o1 = make_float4(v[4] + bias1.x, v[5] + bias1.y, v[6] + bias1.z, v[7] + bias1.w);
            float* p = out + (long long)(base + row) * OUT_F + col0;
            *(float4*)p = o0;
            *(float4*)(p + 4) = o1;
        }
    }
}

// ---------------- edge messages: out[recv] += inv_deg[recv] * (x_src @ W_rel) ----------------
__global__ void __launch_bounds__(256) edge_gemm_k(const float* __restrict__ nf,
                                                   const int* __restrict__ senders,
                                                   const int* __restrict__ receivers,
                                                   float* __restrict__ out) {
    __shared__ float Xs[TE][IN_F];
    __shared__ float Ws[IN_F][OUT_F];
    int b = blockIdx.x;
    if (b >= g_tile_off[N_REL]) return;

    int r = 0;
    while (b >= g_tile_off[r + 1]) r++;

    int seg_s = g_off[r], seg_e = g_off[r + 1];
    int base = seg_s + (b - g_tile_off[r]) * TE;
    int nE = min(TE, seg_e - base);
    int tid = threadIdx.x;

    {
        const float4* s4 = (const float4*)(g_W + r * IN_F * OUT_F);
        float4* d4 = (float4*)&Ws[0][0];
        for (int i = tid; i < IN_F * OUT_F / 4; i += blockDim.x) d4[i] = s4[i];
    }
    {
        int row = tid & (TE - 1);
        int half = tid >> 7;
        if (row < nE) {
            int s = senders[g_sorted[base + row]];
            const float4* src = (const float4*)nf + (long long)s * (IN_F / 4) + half * 8;
            float4* dst = (float4*)Xs[row];
            int swz = (row >> 2) & 3;
            #pragma unroll
            for (int c = 0; c < 8; c++) dst[(half * 8 + c) ^ swz] = src[c];
        }
    }
    __syncthreads();

    int tx = tid & 7, ty = tid >> 3;
    int row0 = ty * 4, col0 = tx * 8;
    unsigned long long acc[4][4];
    gemm_core(Xs, Ws, row0, col0, ty & 3, acc);

    #pragma unroll
    for (int r4 = 0; r4 < 4; r4++) {
        int row = row0 + r4;
        if (row < nE) {
            int e = g_sorted[base + row];
            int rc = receivers[e];
            float inv = g_inv[rc];
            float v[8];
            f2unpack(acc[r4][0], v[0], v[1]);
            f2unpack(acc[r4][1], v[2], v[3]);
            f2unpack(acc[r4][2], v[4], v[5]);
            f2unpack(acc[r4][3], v[6], v[7]);
            float* p = out + (long long)rc * OUT_F + col0;
            red4(p,     v[0] * inv, v[1] * inv, v[2] * inv, v[3] * inv);
            red4(p + 4, v[4] * inv, v[5] * inv, v[6] * inv, v[7] * inv);
        }
    }
}

// ---------------- launch ----------------
extern "C" void kernel_launch(void* const* d_in, const int* in_sizes, int n_in,
                              void* d_out, int out_size) {
    const float* node_features = (const float*)d_in[0];
    const int*   senders       = (const int*)d_in[1];
    const int*   receivers     = (const int*)d_in[2];
    const int*   rel_types     = (const int*)d_in[3];
    const float* basis         = (const float*)d_in[4];
    const float* coeff         = (const float*)d_in[5];
    const float* self_weight   = (const float*)d_in[6];
    const float* bias          = (const float*)d_in[7];
    float* out = (float*)d_out;

    int N = in_sizes[0] / IN_F;
    int E = in_sizes[1];
    if (N > MAX_NODES) N = MAX_NODES;
    if (E > MAX_EDGES) E = MAX_EDGES;

    int nzero = (N > N_REL ? N : N_REL);
    zero_k<<<(nzero + 255) / 256, 256>>>(N);
    compute_W_k<<<N_REL, 256>>>(basis, coeff);
    hist_deg_k<<<512, 256>>>(rel_types, receivers, E);
    prefix_k<<<1, 1>>>();
    scatter_k<<<512, 256>>>(rel_types, E);
    inv_k<<<(N + 255) / 256, 256>>>(N);
    self_gemm_k<<<(N + TE - 1) / TE, 256>>>(node_features, self_weight, bias, out, N);

    int max_tiles = (E + TE - 1) / TE + N_REL;
    edge_gemm_k<<<max_tiles, 256>>>(node_features, senders, receivers, out);
}

// round 5
// speedup vs baseline: 2.0037x; 2.0037x over previous
#include <cuda_runtime.h>
#include <cuda_bf16.h>
#include <cstdint>

#define N_REL   32
#define N_BASES 30
#define IN_F    64
#define OUT_F   64
#define MAX_NODES 100000
#define MAX_EDGES 1000000
#define TE      128   // edges (rows) per tile

// ---------------- device scratch (static, allocation-free) ----------------
__device__ __nv_bfloat16  g_Wbf[N_REL * OUT_F * IN_F];   // bf16, TRANSPOSED: [r][o][i]
__device__ float g_deg[MAX_NODES];
__device__ float g_inv[MAX_NODES];
__device__ int   g_hist[N_REL];
__device__ int   g_off[N_REL + 1];
__device__ int   g_cursor[N_REL];
__device__ int   g_tile_off[N_REL + 1];
__device__ int   g_sorted[MAX_EDGES];

// ---------------- helpers ----------------
__device__ __forceinline__ uint32_t smem_u32(const void* p) {
    uint32_t a;
    asm("{ .reg .u64 t; cvta.to.shared.u64 t, %1; cvt.u32.u64 %0, t; }" : "=r"(a) : "l"(p));
    return a;
}
__device__ __forceinline__ uint32_t bf2pack(float lo, float hi) {
    uint32_t r;
    asm("cvt.rn.bf16x2.f32 %0, %1, %2;" : "=r"(r) : "f"(hi), "f"(lo));
    return r;
}
__device__ __forceinline__ void sts128(uint32_t addr, uint32_t a, uint32_t b, uint32_t c, uint32_t d) {
    asm volatile("st.shared.v4.b32 [%0], {%1, %2, %3, %4};" :: "r"(addr), "r"(a), "r"(b), "r"(c), "r"(d) : "memory");
}
__device__ __forceinline__ void red2(float* p, float a, float b) {
    asm volatile("red.global.add.v2.f32 [%0], {%1, %2};" :: "l"(p), "f"(a), "f"(b) : "memory");
}
__device__ __forceinline__ unsigned long long f2pack(float lo, float hi) {
    unsigned long long r;
    asm("mov.b64 %0, {%1, %2};" : "=l"(r) : "f"(lo), "f"(hi));
    return r;
}
__device__ __forceinline__ void f2unpack(unsigned long long v, float& lo, float& hi) {
    asm("mov.b64 {%0, %1}, %2;" : "=f"(lo), "=f"(hi) : "l"(v));
}
__device__ __forceinline__ unsigned long long ffma2(unsigned long long a, unsigned long long b,
                                                    unsigned long long c) {
    unsigned long long d;
    asm("fma.rn.f32x2 %0, %1, %2, %3;" : "=l"(d) : "l"(a), "l"(b), "l"(c));
    return d;
}
__device__ __forceinline__ void ldm_x4(uint32_t& r0, uint32_t& r1, uint32_t& r2, uint32_t& r3,
                                       uint32_t addr) {
    asm volatile("ldmatrix.sync.aligned.m8n8.x4.shared.b16 {%0, %1, %2, %3}, [%4];"
                 : "=r"(r0), "=r"(r1), "=r"(r2), "=r"(r3) : "r"(addr));
}
__device__ __forceinline__ void mma_bf16(float* d, uint32_t a0, uint32_t a1, uint32_t a2,
                                         uint32_t a3, uint32_t b0, uint32_t b1) {
    asm volatile("mma.sync.aligned.m16n8k16.row.col.f32.bf16.bf16.f32 "
                 "{%0, %1, %2, %3}, {%4, %5, %6, %7}, {%8, %9}, {%0, %1, %2, %3};"
                 : "+f"(d[0]), "+f"(d[1]), "+f"(d[2]), "+f"(d[3])
                 : "r"(a0), "r"(a1), "r"(a2), "r"(a3), "r"(b0), "r"(b1));
}

#define SW128(o) ((o) ^ (((o) >> 3) & 0x70))

// ---------------- small pipeline kernels ----------------
__global__ void zero_k(int n_nodes) {
    int i = blockIdx.x * blockDim.x + threadIdx.x;
    if (i < n_nodes) g_deg[i] = 0.f;
    if (i < N_REL)   g_hist[i] = 0;
}

__global__ void compute_W_k(const float* __restrict__ basis, const float* __restrict__ coeff) {
    int r = blockIdx.x;
    __shared__ float c[N_BASES];
    if (threadIdx.x < N_BASES) c[threadIdx.x] = coeff[r * N_BASES + threadIdx.x];
    __syncthreads();
    for (int idx = threadIdx.x; idx < IN_F * OUT_F; idx += blockDim.x) {
        float acc = 0.f;
        #pragma unroll
        for (int b = 0; b < N_BASES; b++)
            acc += c[b] * basis[b * IN_F * OUT_F + idx];
        int i = idx / OUT_F, o = idx % OUT_F;
        g_Wbf[r * IN_F * OUT_F + o * IN_F + i] = __float2bfloat16(acc);  // store W^T
    }
}

__global__ void hist_deg_k(const int* __restrict__ rel, const int* __restrict__ recv, int E) {
    __shared__ int h[N_REL];
    if (threadIdx.x < N_REL) h[threadIdx.x] = 0;
    __syncthreads();
    for (int e = blockIdx.x * blockDim.x + threadIdx.x; e < E; e += gridDim.x * blockDim.x) {
        atomicAdd(&h[rel[e]], 1);
        atomicAdd(&g_deg[recv[e]], 1.f);
    }
    __syncthreads();
    if (threadIdx.x < N_REL) atomicAdd(&g_hist[threadIdx.x], h[threadIdx.x]);
}

__global__ void prefix_k() {
    int off = 0, toff = 0;
    g_off[0] = 0;
    g_tile_off[0] = 0;
    for (int r = 0; r < N_REL; r++) {
        int c = g_hist[r];
        g_cursor[r] = off;
        off += c;
        g_off[r + 1] = off;
        toff += (c + TE - 1) / TE;
        g_tile_off[r + 1] = toff;
    }
}

__global__ void scatter_k(const int* __restrict__ rel, int E) {
    __shared__ int cnt[N_REL];
    __shared__ int base[N_REL];
    int chunk = (E + gridDim.x - 1) / gridDim.x;
    int s = blockIdx.x * chunk;
    int e_end = min(E, s + chunk);
    if (threadIdx.x < N_REL) cnt[threadIdx.x] = 0;
    __syncthreads();
    for (int i = s + threadIdx.x; i < e_end; i += blockDim.x)
        atomicAdd(&cnt[rel[i]], 1);
    __syncthreads();
    if (threadIdx.x < N_REL)
        base[threadIdx.x] = atomicAdd(&g_cursor[threadIdx.x], cnt[threadIdx.x]);
    __syncthreads();
    if (threadIdx.x < N_REL) cnt[threadIdx.x] = 0;
    __syncthreads();
    for (int i = s + threadIdx.x; i < e_end; i += blockDim.x) {
        int r = rel[i];
        int p = atomicAdd(&cnt[r], 1);
        g_sorted[base[r] + p] = i;
    }
}

__global__ void inv_k(int n) {
    int i = blockIdx.x * blockDim.x + threadIdx.x;
    if (i < n) g_inv[i] = 1.f / fmaxf(g_deg[i], 1.f);
}

// ---------------- self term (fp32 for precision): out = X @ self_weight + bias ----------------
__device__ __forceinline__ void gemm_core(const float (&Xs)[TE][IN_F],
                                          const float (&Ws)[IN_F][OUT_F],
                                          int row0, int col0, int sw_x,
                                          unsigned long long (&acc)[4][4]) {
    #pragma unroll
    for (int i = 0; i < 4; i++)
        #pragma unroll
        for (int j = 0; j < 4; j++) acc[i][j] = 0ull;

    for (int k = 0; k < IN_F; k += 4) {
        float4 a[4];
        #pragma unroll
        for (int r4 = 0; r4 < 4; r4++)
            a[r4] = ((const float4*)Xs[row0 + r4])[(k >> 2) ^ sw_x];
        #pragma unroll
        for (int u = 0; u < 4; u++) {
            float4 b0 = *(const float4*)&Ws[k + u][col0];
            float4 b1 = *(const float4*)&Ws[k + u][col0 + 4];
            unsigned long long bp0 = f2pack(b0.x, b0.y);
            unsigned long long bp1 = f2pack(b0.z, b0.w);
            unsigned long long bp2 = f2pack(b1.x, b1.y);
            unsigned long long bp3 = f2pack(b1.z, b1.w);
            #pragma unroll
            for (int r4 = 0; r4 < 4; r4++) {
                float av = (u == 0) ? a[r4].x : (u == 1) ? a[r4].y : (u == 2) ? a[r4].z : a[r4].w;
                unsigned long long ap = f2pack(av, av);
                acc[r4][0] = ffma2(ap, bp0, acc[r4][0]);
                acc[r4][1] = ffma2(ap, bp1, acc[r4][1]);
                acc[r4][2] = ffma2(ap, bp2, acc[r4][2]);
                acc[r4][3] = ffma2(ap, bp3, acc[r4][3]);
            }
        }
    }
}

__global__ void __launch_bounds__(256) self_gemm_k(const float* __restrict__ nf,
                                                   const float* __restrict__ sw,
                                                   const float* __restrict__ bias,
                                                   float* __restrict__ out, int N) {
    __shared__ float Xs[TE][IN_F];
    __shared__ float Ws[IN_F][OUT_F];
    int tid = threadIdx.x;
    int base = blockIdx.x * TE;
    int nR = min(TE, N - base);

    {
        const float4* s4 = (const float4*)sw;
        float4* d4 = (float4*)&Ws[0][0];
        for (int i = tid; i < IN_F * OUT_F / 4; i += blockDim.x) d4[i] = s4[i];
    }
    {
        int row = tid & (TE - 1);
        int half = tid >> 7;
        if (row < nR) {
            const float4* src = (const float4*)nf + (long long)(base + row) * (IN_F / 4) + half * 8;
            float4* dst = (float4*)Xs[row];
            int swz = (row >> 2) & 3;
            #pragma unroll
            for (int c = 0; c < 8; c++) dst[(half * 8 + c) ^ swz] = src[c];
        }
    }
    __syncthreads();

    int tx = tid & 7, ty = tid >> 3;
    int row0 = ty * 4, col0 = tx * 8;
    unsigned long long acc[4][4];
    gemm_core(Xs, Ws, row0, col0, ty & 3, acc);

    float4 bias0 = *(const float4*)&bias[col0];
    float4 bias1 = *(const float4*)&bias[col0 + 4];
    #pragma unroll
    for (int r4 = 0; r4 < 4; r4++) {
        int row = row0 + r4;
        if (row < nR) {
            float v[8];
            f2unpack(acc[r4][0], v[0], v[1]);
            f2unpack(acc[r4][1], v[2], v[3]);
            f2unpack(acc[r4][2], v[4], v[5]);
            f2unpack(acc[r4][3], v[6], v[7]);
            float4 o0 = make_float4(v[0] + bias0.x, v[1] + bias0.y, v[2] + bias0.z, v[3] + bias0.w);
            float4 o1 = make_float4(v[4] + bias1.x, v[5] + bias1.y, v[6] + bias1.z, v[7] + bias1.w);
            float* p = out + (long long)(base + row) * OUT_F + col0;
            *(float4*)p = o0;
            *(float4*)(p + 4) = o1;
        }
    }
}

// ---------------- edge messages via mma.sync bf16 (HMMA) ----------------
// Tile: D[128 edges, 64 out] = A[128, 64](bf16, SW128 SMEM) @ W_r (B = W^T, n-major
// rows of contiguous k -> "col" operand of m16n8k16). 4 warps: warp w owns rows
// [32w, 32w+32). Epilogue scatters D frags scaled by inv_deg via red.global.add.v2.
__global__ void __launch_bounds__(128, 4)
edge_mma_k(const float* __restrict__ nf,
           const int* __restrict__ senders,
           const int* __restrict__ receivers,
           float* __restrict__ out) {
    __shared__ __align__(128) uint8_t sAB[TE * 128 + OUT_F * 128];  // A: 16KB, B: 8KB
    __shared__ int   s_rc[TE];
    __shared__ float s_inv[TE];

    int b = blockIdx.x;
    if (b >= g_tile_off[N_REL]) return;

    int r = 0;
    while (b >= g_tile_off[r + 1]) r++;
    int base = g_off[r] + (b - g_tile_off[r]) * TE;
    int nE = min(TE, g_off[r + 1] - base);

    int tid  = threadIdx.x;
    int w    = tid >> 5;
    int lane = tid & 31;

    uint32_t sA = smem_u32(sAB);
    uint32_t sB = sA + TE * 128;

    // Stage B = W_r^T bf16 (64 rows x 128B), SW128-swizzled
    {
        const uint4* wsrc = (const uint4*)(g_Wbf + (size_t)r * IN_F * OUT_F);
        #pragma unroll
        for (int i = tid; i < 512; i += 128) {
            uint4 v = wsrc[i];
            uint32_t off = (uint32_t)i * 16u;
            sts128(sB + SW128(off), v.x, v.y, v.z, v.w);
        }
    }

    // Gather A: thread tid owns edge-row tid. Convert fp32 -> bf16, SW128 store.
    // Rows beyond nE are zero-filled so partial tiles never feed garbage/NaN to MMA.
    {
        uint32_t rowbase = (uint32_t)tid * 128u;
        if (tid < nE) {
            int e = g_sorted[base + tid];
            int s = senders[e];
            int rc = receivers[e];
            s_rc[tid]  = rc;
            s_inv[tid] = g_inv[rc];
            const float4* src = (const float4*)(nf + (size_t)s * IN_F);
            #pragma unroll
            for (int c = 0; c < 8; c++) {
                float4 f0 = src[2 * c];
                float4 f1 = src[2 * c + 1];
                uint32_t p0 = bf2pack(f0.x, f0.y);
                uint32_t p1 = bf2pack(f0.z, f0.w);
                uint32_t p2 = bf2pack(f1.x, f1.y);
                uint32_t p3 = bf2pack(f1.z, f1.w);
                uint32_t off = rowbase + (uint32_t)c * 16u;
                sts128(sA + SW128(off), p0, p1, p2, p3);
            }
        } else {
            #pragma unroll
            for (int c = 0; c < 8; c++) {
                uint32_t off = rowbase + (uint32_t)c * 16u;
                sts128(sA + SW128(off), 0u, 0u, 0u, 0u);
            }
        }
    }
    __syncthreads();

    // MMA mainloop: 2 m-tiles x 8 n-tiles x 4 k-steps of m16n8k16
    float acc[2][8][4];
    #pragma unroll
    for (int mt = 0; mt < 2; mt++)
        #pragma unroll
        for (int j = 0; j < 8; j++)
            #pragma unroll
            for (int q = 0; q < 4; q++) acc[mt][j][q] = 0.f;

    #pragma unroll
    for (int k = 0; k < 4; k++) {
        // A fragments. ldmatrix.x4 matrix order = lane groups 0-7/8-15/16-23/24-31.
        // Required: a0=(r0-7,k0-7), a1=(r8-15,k0-7), a2=(r0-7,k8-15), a3=(r8-15,k8-15)
        // -> lanes 8-15 select row+8 ((lane>>3)&1), lanes 16-31 select k+16 ((lane>>4)&1).
        uint32_t a[2][4];
        #pragma unroll
        for (int mt = 0; mt < 2; mt++) {
            uint32_t row = (uint32_t)(w * 32 + mt * 16 + (((lane >> 3) & 1) << 3) + (lane & 7));
            uint32_t kb  = (uint32_t)(32 * k + (((lane >> 4) & 1) << 4));
            uint32_t off = row * 128u + kb;
            ldm_x4(a[mt][0], a[mt][1], a[mt][2], a[mt][3], sA + SW128(off));
        }
        // B fragments: 8 n-tiles, 2 regs each; x4 covers 2 n-tiles.
        // Order: m0=(n0,k0-7), m1=(n0,k8-15), m2=(n1,k0-7), m3=(n1,k8-15)
        // -> lanes 8-15 select k+16 ((lane>>3)&1), lanes 16-31 select next n-tile ((lane>>4)&1).
        uint32_t bf[8][2];
        #pragma unroll
        for (int jp = 0; jp < 4; jp++) {
            uint32_t jl   = (uint32_t)((lane >> 4) & 1);
            uint32_t half = (uint32_t)((lane >> 3) & 1);
            uint32_t rowb = (uint32_t)(8 * (2 * jp + jl) + (lane & 7));
            uint32_t kb   = (uint32_t)(32 * k + 16 * half);
            uint32_t off  = rowb * 128u + kb;
            ldm_x4(bf[2 * jp][0], bf[2 * jp][1], bf[2 * jp + 1][0], bf[2 * jp + 1][1],
                   sB + SW128(off));
        }
        #pragma unroll
        for (int mt = 0; mt < 2; mt++)
            #pragma unroll
            for (int j = 0; j < 8; j++)
                mma_bf16(acc[mt][j], a[mt][0], a[mt][1], a[mt][2], a[mt][3],
                         bf[j][0], bf[j][1]);
    }

    // Epilogue: D frag (g, 2tg)/(g,2tg+1)/(g+8,2tg)/(g+8,2tg+1); scale by inv, red.v2
    int g  = lane >> 2;
    int tg = lane & 3;
    #pragma unroll
    for (int mt = 0; mt < 2; mt++) {
        int r1 = w * 32 + mt * 16 + g;
        int r2 = r1 + 8;
        bool v1 = r1 < nE, v2 = r2 < nE;
        float inv1 = 0.f, inv2 = 0.f;
        int   rc1 = 0, rc2 = 0;
        if (v1) { rc1 = s_rc[r1]; inv1 = s_inv[r1]; }
        if (v2) { rc2 = s_rc[r2]; inv2 = s_inv[r2]; }
        float* p1 = out + (size_t)rc1 * OUT_F + 2 * tg;
        float* p2 = out + (size_t)rc2 * OUT_F + 2 * tg;
        #pragma unroll
        for (int j = 0; j < 8; j++) {
            if (v1) red2(p1 + 8 * j, acc[mt][j][0] * inv1, acc[mt][j][1] * inv1);
            if (v2) red2(p2 + 8 * j, acc[mt][j][2] * inv2, acc[mt][j][3] * inv2);
        }
    }
}

// ---------------- launch ----------------
extern "C" void kernel_launch(void* const* d_in, const int* in_sizes, int n_in,
                              void* d_out, int out_size) {
    const float* node_features = (const float*)d_in[0];
    const int*   senders       = (const int*)d_in[1];
    const int*   receivers     = (const int*)d_in[2];
    const int*   rel_types     = (const int*)d_in[3];
    const float* basis         = (const float*)d_in[4];
    const float* coeff         = (const float*)d_in[5];
    const float* self_weight   = (const float*)d_in[6];
    const float* bias          = (const float*)d_in[7];
    float* out = (float*)d_out;

    int N = in_sizes[0] / IN_F;
    int E = in_sizes[1];
    if (N > MAX_NODES) N = MAX_NODES;
    if (E > MAX_EDGES) E = MAX_EDGES;

    int nzero = (N > N_REL ? N : N_REL);
    zero_k<<<(nzero + 255) / 256, 256>>>(N);
    compute_W_k<<<N_REL, 256>>>(basis, coeff);
    hist_deg_k<<<512, 256>>>(rel_types, receivers, E);
    prefix_k<<<1, 1>>>();
    scatter_k<<<512, 256>>>(rel_types, E);
    inv_k<<<(N + 255) / 256, 256>>>(N);
    self_gemm_k<<<(N + TE - 1) / TE, 256>>>(node_features, self_weight, bias, out, N);

    int max_tiles = (E + TE - 1) / TE + N_REL;
    edge_mma_k<<<max_tiles, 128>>>(node_features, senders, receivers, out);
}